// round 16
// baseline (speedup 1.0000x reference)
#include <cuda_runtime.h>
#include <cuda_fp16.h>
#include <math.h>
#include <stdint.h>

#define SEQ    2048
#define DMODEL 2048
#define NH     32
#define NKV    8
#define HD     64
#define KVD    (NKV*HD)   // 512

// -------------------- scratch (no allocs allowed) --------------------
__device__ float g_cos[SEQ*(HD/2)];
__device__ float g_sin[SEQ*(HD/2)];

__device__ __half g_xhi[SEQ*DMODEL];
__device__ __half g_wqhi[DMODEL*DMODEL];
__device__ __half g_wkhi[KVD*DMODEL];
__device__ __half g_wvhi[KVD*DMODEL];
__device__ __half g_wohi[DMODEL*DMODEL];
__device__ __half g_chi[SEQ*DMODEL];
__device__ __half g_qh[SEQ*DMODEL];
__device__ __half g_kh[SEQ*KVD];
__device__ __half g_vh[SEQ*KVD];

// ==================== helpers ====================
__device__ __forceinline__ uint32_t smem_u32(const void* p) {
    uint32_t a;
    asm("{ .reg .u64 t; cvta.to.shared.u64 t, %1; cvt.u32.u64 %0, t; }"
        : "=r"(a) : "l"(p));
    return a;
}

#define CP_ASYNC16(dst, src) \
    asm volatile("cp.async.cg.shared.global [%0], [%1], 16;" :: "r"(dst), "l"(src) : "memory")
#define CP_COMMIT() asm volatile("cp.async.commit_group;" ::: "memory")
#define CP_WAIT_0() asm volatile("cp.async.wait_group 0;" ::: "memory")

#define LDSM4(r0, r1, r2, r3, addr) \
    asm volatile("ldmatrix.sync.aligned.m8n8.x4.shared.b16 {%0,%1,%2,%3}, [%4];" \
        : "=r"(r0), "=r"(r1), "=r"(r2), "=r"(r3) : "r"(addr))

#define LDSM4T(r0, r1, r2, r3, addr) \
    asm volatile("ldmatrix.sync.aligned.m8n8.x4.trans.shared.b16 {%0,%1,%2,%3}, [%4];" \
        : "=r"(r0), "=r"(r1), "=r"(r2), "=r"(r3) : "r"(addr))

#define MMA16816(d, a, b0, b1) \
    asm volatile("mma.sync.aligned.m16n8k16.row.col.f32.f16.f16.f32 " \
        "{%0,%1,%2,%3}, {%4,%5,%6,%7}, {%8,%9}, {%0,%1,%2,%3};" \
        : "+f"((d)[0]), "+f"((d)[1]), "+f"((d)[2]), "+f"((d)[3]) \
        : "r"((a)[0]), "r"((a)[1]), "r"((a)[2]), "r"((a)[3]), "r"(b0), "r"(b1))

// ==================== prep: converts (weights + x) + rope table ====================
__device__ __forceinline__ void conv4(const float* __restrict__ src,
                                      __half* __restrict__ hi, int i) {
    float4 x = ((const float4*)src)[i];
    __half2* hp = (__half2*)(hi + i * 4);
    hp[0] = __half2(__float2half_rn(x.x), __float2half_rn(x.y));
    hp[1] = __half2(__float2half_rn(x.z), __float2half_rn(x.w));
}

#define WQ4 (DMODEL*DMODEL/4)
#define WK4 (KVD*DMODEL/4)
#define X4  (SEQ*DMODEL/4)
#define CONV_END (2*WQ4 + 2*WK4 + X4)
#define TOTAL_PREP (CONV_END + SEQ*32)
__global__ void prep_kernel(const float* __restrict__ Wq, const float* __restrict__ Wk,
                            const float* __restrict__ Wv, const float* __restrict__ Wo,
                            const float* __restrict__ x, const int* __restrict__ start_pos,
                            __half* __restrict__ qh, __half* __restrict__ kh,
                            __half* __restrict__ vh, __half* __restrict__ oh,
                            __half* __restrict__ xh) {
    int i = blockIdx.x * blockDim.x + threadIdx.x;
    if (i < WQ4)                     { conv4(Wq, qh, i); return; }
    if (i < WQ4 + WK4)               { conv4(Wk, kh, i - WQ4); return; }
    if (i < WQ4 + 2*WK4)             { conv4(Wv, vh, i - WQ4 - WK4); return; }
    if (i < 2*WQ4 + 2*WK4)           { conv4(Wo, oh, i - WQ4 - 2*WK4); return; }
    if (i < CONV_END)                { conv4(x, xh, i - 2*WQ4 - 2*WK4); return; }
    if (i >= TOTAL_PREP) return;
    int idx = i - CONV_END;
    int t = idx >> 5, j = idx & 31;
    const double PI = 3.14159265358979323846;
    double e = (double)(2 * j) / 64.0;
    double invf = pow(500000.0, -e);
    double wavelen = 2.0 * PI / invf;
    double inv;
    if (wavelen > 8192.0)      inv = invf / 32.0;
    else if (wavelen < 2048.0) inv = invf;
    else {
        double smooth = (8192.0 / wavelen - 1.0) / 3.0;
        inv = (1.0 - smooth) * (invf / 32.0) + smooth * invf;
    }
    float angle = (float)(start_pos[0] + t) * (float)inv;
    g_cos[idx] = (float)cos((double)angle);
    g_sin[idx] = (float)sin((double)angle);
}

// ==================== QKV GEMM: 128x64 tiles, full K, fused rope epilogue ====================
#define BK 32
#define ASTRH 40
#define ATILE (128 * ASTRH * 2)     // 10240 B
#define BTILE (64 * ASTRH * 2)      // 5120 B
#define QSTG  (ATILE + BTILE)       // 15360 B per stage
#define QKV_SMEM (128 * 66 * 4)     // 33792 epilogue stage > 2*QSTG=30720

__global__ void __launch_bounds__(256, 2) gemm_qkv(
    const __half* __restrict__ Ahi,
    const __half* __restrict__ Bq, const __half* __restrict__ Bk,
    const __half* __restrict__ Bv,
    __half* __restrict__ Oq, __half* __restrict__ Ok, __half* __restrict__ Ov) {
    extern __shared__ __half gsm[];
    const int bx = blockIdx.x;
    const __half* Bh; __half* Out; int Nc, bnl, mode;
    if (bx < 32)      { Bh = Bq; Out = Oq; Nc = DMODEL; bnl = bx * 64;        mode = 0; }
    else if (bx < 40) { Bh = Bk; Out = Ok; Nc = KVD;    bnl = (bx - 32) * 64; mode = 1; }
    else              { Bh = Bv; Out = Ov; Nc = KVD;    bnl = (bx - 40) * 64; mode = 2; }
    const int K = DMODEL;

    const int tid = threadIdx.x;
    const int wid = tid >> 5, lane = tid & 31;
    const int wm = (wid & 3) * 32;       // 4 warps down M (128)
    const int wn = (wid >> 2) * 32;      // 2 warps across N (64)
    const int bm = blockIdx.y * 128;
    const int lr = lane & 15, lc = lane >> 4;

    uint32_t sbu = smem_u32(gsm);
    const int r0_ = tid >> 2, r1_ = r0_ + 64;
    const int pp = (tid & 3) * 8;

    float acc[2][4][4];
#pragma unroll
    for (int a = 0; a < 2; a++)
#pragma unroll
        for (int b = 0; b < 4; b++)
#pragma unroll
            for (int c = 0; c < 4; c++) acc[a][b][c] = 0.f;

#define QLOAD(st, k0) do {                                                      \
    uint32_t _b = sbu + (st) * QSTG;                                            \
    CP_ASYNC16(_b + (r0_ * ASTRH + pp) * 2,                                     \
               Ahi + (size_t)(bm + r0_) * K + (k0) + pp);                       \
    CP_ASYNC16(_b + (r1_ * ASTRH + pp) * 2,                                     \
               Ahi + (size_t)(bm + r1_) * K + (k0) + pp);                       \
    CP_ASYNC16(_b + ATILE + (r0_ * ASTRH + pp) * 2,                             \
               Bh + (size_t)(bnl + r0_) * K + (k0) + pp);                       \
} while (0)

    const int kiters = K / BK;
    QLOAD(0, 0);
    CP_COMMIT();

    for (int i = 0; i < kiters; i++) {
        int s = i & 1;
        CP_WAIT_0();
        __syncthreads();
        if (i + 1 < kiters) {
            QLOAD(s ^ 1, (i + 1) * BK);
            CP_COMMIT();
        }

        uint32_t base = sbu + s * QSTG;
#pragma unroll
        for (int k16 = 0; k16 < 2; k16++) {
            int koff16 = k16 * 16 + lc * 8;
            uint32_t aH[2][4], bH[2][4];
#pragma unroll
            for (int mt = 0; mt < 2; mt++) {
                uint32_t adr = base + ((wm + mt * 16 + lr) * ASTRH + koff16) * 2;
                LDSM4(aH[mt][0], aH[mt][1], aH[mt][2], aH[mt][3], adr);
            }
#pragma unroll
            for (int p = 0; p < 2; p++) {
                uint32_t adr = base + ATILE + ((wn + p * 16 + lr) * ASTRH + koff16) * 2;
                LDSM4(bH[p][0], bH[p][1], bH[p][2], bH[p][3], adr);
            }
#pragma unroll
            for (int mt = 0; mt < 2; mt++)
#pragma unroll
                for (int nt = 0; nt < 4; nt++) {
                    int p = nt >> 1, w = nt & 1;
                    MMA16816(acc[mt][nt], aH[mt], bH[p][w], bH[p][w + 2]);
                }
        }
    }

    // ---- fused epilogue: acc -> smem fp32 (128x66) -> rope/convert -> fp16 ----
    __syncthreads();
    float* se = (float*)gsm;
    int er = lane >> 2, ec = (lane & 3) * 2;
#pragma unroll
    for (int mt = 0; mt < 2; mt++)
#pragma unroll
        for (int nt = 0; nt < 4; nt++) {
            int r = wm + mt * 16 + er;
            int c = wn + nt * 8 + ec;
            se[r * 66 + c]           = acc[mt][nt][0];
            se[r * 66 + c + 1]       = acc[mt][nt][1];
            se[(r + 8) * 66 + c]     = acc[mt][nt][2];
            se[(r + 8) * 66 + c + 1] = acc[mt][nt][3];
        }
    __syncthreads();

    if (mode < 2) {   // rope: tile is exactly one head (64 wide)
#pragma unroll
        for (int l = 0; l < 16; l++) {
            int p = tid + l * 256;       // 0..4095
            int r = p >> 5;              // 0..127
            int j = p & 31;              // rope pair index
            int t = bm + r;
            float c0 = g_cos[t * 32 + j], s0 = g_sin[t * 32 + j];
            float x1 = se[r * 66 + j];
            float x2 = se[r * 66 + j + 32];
            size_t rowb = (size_t)t * Nc + bnl;
            Out[rowb + j]      = __float2half_rn(x1 * c0 - x2 * s0);
            Out[rowb + j + 32] = __float2half_rn(x2 * c0 + x1 * s0);
        }
    } else {          // v: plain convert, half2 stores
#pragma unroll
        for (int l = 0; l < 16; l++) {
            int p = tid + l * 256;       // 0..4095 half2 slots
            int r = p >> 5;
            int cc = (p & 31) * 2;
            __half2 h = __floats2half2_rn(se[r * 66 + cc], se[r * 66 + cc + 1]);
            *(__half2*)&Out[(size_t)(bm + r) * Nc + bnl + cc] = h;
        }
    }
}

// ==================== O-projection GEMM (fp32 out, 128x128) ====================
#define TILEB (128 * ASTRH * 2)
#define GSMEM (TILEB * 4)

__global__ void __launch_bounds__(256, 2) gemm_o(
    const __half* __restrict__ Ahi,
    const __half* __restrict__ Bh,
    float* __restrict__ C, int N, int K) {
    extern __shared__ __half gsm[];
    const int bnl = blockIdx.x * 128;

    const int tid = threadIdx.x;
    const int wid = tid >> 5, lane = tid & 31;
    const int wm = (wid & 1) * 64;
    const int wn = (wid >> 1) * 32;
    const int bm = blockIdx.y * 128;
    const int lr = lane & 15, lc = lane >> 4;

    uint32_t sbu = smem_u32(gsm);
    const int r0_ = tid >> 2, r1_ = r0_ + 64;
    const int pp = (tid & 3) * 8;

    float acc[4][4][4];
#pragma unroll
    for (int a = 0; a < 4; a++)
#pragma unroll
        for (int b = 0; b < 4; b++)
#pragma unroll
            for (int c = 0; c < 4; c++) acc[a][b][c] = 0.f;

#define OLOAD(st, k0) do {                                                      \
    uint32_t _b = sbu + (st) * (2 * TILEB);                                     \
    CP_ASYNC16(_b + (r0_ * ASTRH + pp) * 2,                                     \
               Ahi + (size_t)(bm + r0_) * K + (k0) + pp);                       \
    CP_ASYNC16(_b + (r1_ * ASTRH + pp) * 2,                                     \
               Ahi + (size_t)(bm + r1_) * K + (k0) + pp);                       \
    CP_ASYNC16(_b + TILEB + (r0_ * ASTRH + pp) * 2,                             \
               Bh + (size_t)(bnl + r0_) * K + (k0) + pp);                       \
    CP_ASYNC16(_b + TILEB + (r1_ * ASTRH + pp) * 2,                             \
               Bh + (size_t)(bnl + r1_) * K + (k0) + pp);                       \
} while (0)

    const int kiters = K / BK;
    OLOAD(0, 0);
    CP_COMMIT();

    for (int i = 0; i < kiters; i++) {
        int s = i & 1;
        CP_WAIT_0();
        __syncthreads();
        if (i + 1 < kiters) {
            OLOAD(s ^ 1, (i + 1) * BK);
            CP_COMMIT();
        }

        uint32_t base = sbu + s * (2 * TILEB);
#pragma unroll
        for (int k16 = 0; k16 < 2; k16++) {
            int koff16 = k16 * 16 + lc * 8;
            uint32_t aH[4][4], bH[2][4];
#pragma unroll
            for (int mt = 0; mt < 4; mt++) {
                uint32_t adr = base + ((wm + mt * 16 + lr) * ASTRH + koff16) * 2;
                LDSM4(aH[mt][0], aH[mt][1], aH[mt][2], aH[mt][3], adr);
            }
#pragma unroll
            for (int p = 0; p < 2; p++) {
                uint32_t adr = base + TILEB + ((wn + p * 16 + lr) * ASTRH + koff16) * 2;
                LDSM4(bH[p][0], bH[p][1], bH[p][2], bH[p][3], adr);
            }
#pragma unroll
            for (int mt = 0; mt < 4; mt++)
#pragma unroll
                for (int nt = 0; nt < 4; nt++) {
                    int p = nt >> 1, w = nt & 1;
                    MMA16816(acc[mt][nt], aH[mt], bH[p][w], bH[p][w + 2]);
                }
        }
    }

    int er = lane >> 2, ec = (lane & 3) * 2;
#pragma unroll
    for (int mt = 0; mt < 4; mt++) {
#pragma unroll
        for (int nt = 0; nt < 4; nt++) {
            int r = bm + wm + mt * 16 + er;
            int c = bnl + wn + nt * 8 + ec;
            *(float2*)&C[(size_t)r * N + c]       = make_float2(acc[mt][nt][0], acc[mt][nt][1]);
            *(float2*)&C[(size_t)(r + 8) * N + c] = make_float2(acc[mt][nt][2], acc[mt][nt][3]);
        }
    }
}

// ==================== HMMA flash attention (1-term) ====================
#define FATR 72
#define FTILE (64 * FATR * 2)
#define FLASH_SMEM (FTILE * 5)   // Qh + 2 stages x (Kh, Vh)

__global__ void __launch_bounds__(128) flash_hmma(
    const __half* __restrict__ qhi,
    const __half* __restrict__ khi,
    const __half* __restrict__ vhi,
    __half* __restrict__ chi) {
    extern __shared__ __half fsm[];
    const int h  = blockIdx.x;
    const int qb = gridDim.y - 1 - blockIdx.y;
    const int g  = h >> 2;
    const int tid = threadIdx.x;
    const int wid = tid >> 5, lane = tid & 31;
    const int wm = wid * 16;
    const int er = lane >> 2, ec = (lane & 3) * 2;
    const int lr = lane & 15, lc = lane >> 4;

    uint32_t sb = smem_u32(fsm);
    uint32_t sQh = sb;

#pragma unroll
    for (int l = 0; l < 4; l++) {
        int c = tid + l * 128;
        int row = c >> 3, cc = c & 7;
        size_t off = (size_t)(qb * 64 + row) * DMODEL + h * 64 + cc * 8;
        CP_ASYNC16(sQh + row * FATR * 2 + cc * 16, qhi + off);
    }
#define KV_LOAD(kb_, st_) do {                                                  \
    uint32_t base = sb + FTILE + (st_) * 2 * FTILE;                             \
    _Pragma("unroll")                                                           \
    for (int l = 0; l < 4; l++) {                                               \
        int c = tid + l * 128;                                                  \
        int row = c >> 3, cc = c & 7;                                           \
        size_t off = (size_t)((kb_) * 64 + row) * KVD + g * 64 + cc * 8;        \
        uint32_t d = row * FATR * 2 + cc * 16;                                  \
        CP_ASYNC16(base + d, khi + off);                                        \
        CP_ASYNC16(base + FTILE + d, vhi + off);                                \
    }                                                                           \
} while (0)

    KV_LOAD(0, 0);
    CP_COMMIT();

    uint32_t aQh[4][4];
    float oacc[8][4];
    float mi0 = -INFINITY, mi1 = -INFINITY, li0 = 0.f, li1 = 0.f;
#pragma unroll
    for (int nt = 0; nt < 8; nt++)
#pragma unroll
        for (int j = 0; j < 4; j++) oacc[nt][j] = 0.f;

    for (int kb = 0; kb <= qb; kb++) {
        int stage = kb & 1;
        CP_WAIT_0();
        __syncthreads();
        if (kb < qb) {
            KV_LOAD(kb + 1, stage ^ 1);
            CP_COMMIT();
        }

        if (kb == 0) {
#pragma unroll
            for (int k16 = 0; k16 < 4; k16++) {
                uint32_t ah = sQh + ((wm + lr) * FATR + k16 * 16 + lc * 8) * 2;
                LDSM4(aQh[k16][0], aQh[k16][1], aQh[k16][2], aQh[k16][3], ah);
            }
        }

        uint32_t base = sb + FTILE + stage * 2 * FTILE;
        uint32_t sKh = base, sVh = base + FTILE;

        float sacc[8][4];
#pragma unroll
        for (int nt = 0; nt < 8; nt++)
#pragma unroll
            for (int j = 0; j < 4; j++) sacc[nt][j] = 0.f;

#pragma unroll
        for (int k16 = 0; k16 < 4; k16++) {
            uint32_t bh[4][4];
#pragma unroll
            for (int p = 0; p < 4; p++) {
                uint32_t adr = sKh + ((p * 16 + lr) * FATR + k16 * 16 + lc * 8) * 2;
                LDSM4(bh[p][0], bh[p][1], bh[p][2], bh[p][3], adr);
            }
#pragma unroll
            for (int nt = 0; nt < 8; nt++) {
                int p = nt >> 1, w = nt & 1;
                MMA16816(sacc[nt], aQh[k16], bh[p][w], bh[p][w + 2]);
            }
        }

        if (kb == qb) {
#pragma unroll
            for (int nt = 0; nt < 8; nt++) {
                int c0 = nt * 8 + ec;
                sacc[nt][0] = (c0     <= wm + er)     ? sacc[nt][0] * 0.125f : -INFINITY;
                sacc[nt][1] = (c0 + 1 <= wm + er)     ? sacc[nt][1] * 0.125f : -INFINITY;
                sacc[nt][2] = (c0     <= wm + er + 8) ? sacc[nt][2] * 0.125f : -INFINITY;
                sacc[nt][3] = (c0 + 1 <= wm + er + 8) ? sacc[nt][3] * 0.125f : -INFINITY;
            }
        } else {
#pragma unroll
            for (int nt = 0; nt < 8; nt++)
#pragma unroll
                for (int j = 0; j < 4; j++) sacc[nt][j] *= 0.125f;
        }

        float mx0 = -INFINITY, mx1 = -INFINITY;
#pragma unroll
        for (int nt = 0; nt < 8; nt++) {
            mx0 = fmaxf(mx0, fmaxf(sacc[nt][0], sacc[nt][1]));
            mx1 = fmaxf(mx1, fmaxf(sacc[nt][2], sacc[nt][3]));
        }
#pragma unroll
        for (int off = 1; off < 4; off <<= 1) {
            mx0 = fmaxf(mx0, __shfl_xor_sync(0xffffffffu, mx0, off));
            mx1 = fmaxf(mx1, __shfl_xor_sync(0xffffffffu, mx1, off));
        }
        float mn0 = fmaxf(mi0, mx0), mn1 = fmaxf(mi1, mx1);
        float sum0 = 0.f, sum1 = 0.f;
#pragma unroll
        for (int nt = 0; nt < 8; nt++) {
            sacc[nt][0] = __expf(sacc[nt][0] - mn0);
            sacc[nt][1] = __expf(sacc[nt][1] - mn0);
            sacc[nt][2] = __expf(sacc[nt][2] - mn1);
            sacc[nt][3] = __expf(sacc[nt][3] - mn1);
            sum0 += sacc[nt][0] + sacc[nt][1];
            sum1 += sacc[nt][2] + sacc[nt][3];
        }
#pragma unroll
        for (int off = 1; off < 4; off <<= 1) {
            sum0 += __shfl_xor_sync(0xffffffffu, sum0, off);
            sum1 += __shfl_xor_sync(0xffffffffu, sum1, off);
        }
        float sc0 = __expf(mi0 - mn0), sc1 = __expf(mi1 - mn1);
        li0 = li0 * sc0 + sum0; li1 = li1 * sc1 + sum1;
        mi0 = mn0; mi1 = mn1;
#pragma unroll
        for (int nt = 0; nt < 8; nt++) {
            oacc[nt][0] *= sc0; oacc[nt][1] *= sc0;
            oacc[nt][2] *= sc1; oacc[nt][3] *= sc1;
        }

#pragma unroll
        for (int k16 = 0; k16 < 4; k16++) {
            uint32_t ph[4];
#pragma unroll
            for (int half16 = 0; half16 < 2; half16++) {
                int st = 2 * k16 + half16;
                __half2 h01 = __floats2half2_rn(sacc[st][0], sacc[st][1]);
                __half2 h23 = __floats2half2_rn(sacc[st][2], sacc[st][3]);
                ph[half16 * 2]     = *(uint32_t*)&h01;
                ph[half16 * 2 + 1] = *(uint32_t*)&h23;
            }
            uint32_t bvh[4][4];
#pragma unroll
            for (int p = 0; p < 4; p++) {
                uint32_t adr = sVh + ((k16 * 16 + lr) * FATR + p * 16 + lc * 8) * 2;
                LDSM4T(bvh[p][0], bvh[p][1], bvh[p][2], bvh[p][3], adr);
            }
#pragma unroll
            for (int nt = 0; nt < 8; nt++) {
                int p = nt >> 1, w = (nt & 1) * 2;
                MMA16816(oacc[nt], ph, bvh[p][w], bvh[p][w + 1]);
            }
        }
    }

    float inv0 = 1.0f / li0, inv1 = 1.0f / li1;
    int r0g = qb * 64 + wm + er, r1g = r0g + 8;
#pragma unroll
    for (int nt = 0; nt < 8; nt++) {
        int c = h * 64 + nt * 8 + ec;
        __half2 h0 = __floats2half2_rn(oacc[nt][0] * inv0, oacc[nt][1] * inv0);
        __half2 h1 = __floats2half2_rn(oacc[nt][2] * inv1, oacc[nt][3] * inv1);
        *(__half2*)&chi[(size_t)r0g * DMODEL + c] = h0;
        *(__half2*)&chi[(size_t)r1g * DMODEL + c] = h1;
    }
}

// -------------------- launch --------------------
extern "C" void kernel_launch(void* const* d_in, const int* in_sizes, int n_in,
                              void* d_out, int out_size) {
    const float* x  = (const float*)d_in[0];
    const float* Wq = (const float*)d_in[1];
    const float* Wk = (const float*)d_in[2];
    const float* Wv = (const float*)d_in[3];
    const float* Wo = (const float*)d_in[4];
    const int* start_pos = (const int*)d_in[5];
    float* out = (float*)d_out;

    __half *xhi, *wqhi, *wkhi, *wvhi, *wohi;
    __half *chi, *qh, *kh, *vh;
    cudaGetSymbolAddress((void**)&xhi, g_xhi);
    cudaGetSymbolAddress((void**)&wqhi, g_wqhi);
    cudaGetSymbolAddress((void**)&wkhi, g_wkhi);
    cudaGetSymbolAddress((void**)&wvhi, g_wvhi);
    cudaGetSymbolAddress((void**)&wohi, g_wohi);
    cudaGetSymbolAddress((void**)&chi, g_chi);
    cudaGetSymbolAddress((void**)&qh, g_qh);
    cudaGetSymbolAddress((void**)&kh, g_kh);
    cudaGetSymbolAddress((void**)&vh, g_vh);

    cudaFuncSetAttribute(gemm_qkv, cudaFuncAttributeMaxDynamicSharedMemorySize, QKV_SMEM);
    cudaFuncSetAttribute(gemm_o, cudaFuncAttributeMaxDynamicSharedMemorySize, GSMEM);
    cudaFuncSetAttribute(flash_hmma, cudaFuncAttributeMaxDynamicSharedMemorySize,
                         FLASH_SMEM);

    // 0: converts (4 weights + x) + rope table
    prep_kernel<<<(TOTAL_PREP + 255) / 256, 256>>>(
        Wq, Wk, Wv, Wo, x, start_pos, wqhi, wkhi, wvhi, wohi, xhi);
    // 1: QKV projection (768 CTAs, 128x64 tiles) with fused rope/convert epilogue
    gemm_qkv<<<dim3(48, SEQ / 128), 256, QKV_SMEM>>>(
        xhi, wqhi, wkhi, wvhi, qh, kh, vh);
    // 2: flash attention
    flash_hmma<<<dim3(NH, SEQ / 64), 128, FLASH_SMEM>>>(qh, kh, vh, chi);
    // 3: O projection -> fp32 out
    gemm_o<<<dim3(16, SEQ / 128), 256, GSMEM>>>(chi, wohi, out, DMODEL, DMODEL);
}

// round 17
// speedup vs baseline: 1.1139x; 1.1139x over previous
#include <cuda_runtime.h>
#include <cuda_fp16.h>
#include <math.h>
#include <stdint.h>

#define SEQ    2048
#define DMODEL 2048
#define NH     32
#define NKV    8
#define HD     64
#define KVD    (NKV*HD)   // 512

// -------------------- scratch (no allocs allowed) --------------------
__device__ float g_q[SEQ*DMODEL],  g_q2[SEQ*DMODEL];
__device__ float g_k[SEQ*KVD],     g_k2[SEQ*KVD];
__device__ float g_v[SEQ*KVD],     g_v2[SEQ*KVD];
__device__ float g_cos[SEQ*(HD/2)];
__device__ float g_sin[SEQ*(HD/2)];

__device__ __half g_xhi[SEQ*DMODEL];
__device__ __half g_wqhi[DMODEL*DMODEL];
__device__ __half g_wkhi[KVD*DMODEL];
__device__ __half g_wvhi[KVD*DMODEL];
__device__ __half g_wohi[DMODEL*DMODEL];
__device__ __half g_chi[SEQ*DMODEL];
__device__ __half g_qh[SEQ*DMODEL];
__device__ __half g_kh[SEQ*KVD];
__device__ __half g_vh[SEQ*KVD];

// ==================== helpers ====================
__device__ __forceinline__ uint32_t smem_u32(const void* p) {
    uint32_t a;
    asm("{ .reg .u64 t; cvta.to.shared.u64 t, %1; cvt.u32.u64 %0, t; }"
        : "=r"(a) : "l"(p));
    return a;
}

#define CP_ASYNC16(dst, src) \
    asm volatile("cp.async.cg.shared.global [%0], [%1], 16;" :: "r"(dst), "l"(src) : "memory")
#define CP_COMMIT() asm volatile("cp.async.commit_group;" ::: "memory")
#define CP_WAIT_0() asm volatile("cp.async.wait_group 0;" ::: "memory")

#define LDSM4(r0, r1, r2, r3, addr) \
    asm volatile("ldmatrix.sync.aligned.m8n8.x4.shared.b16 {%0,%1,%2,%3}, [%4];" \
        : "=r"(r0), "=r"(r1), "=r"(r2), "=r"(r3) : "r"(addr))

#define LDSM4T(r0, r1, r2, r3, addr) \
    asm volatile("ldmatrix.sync.aligned.m8n8.x4.trans.shared.b16 {%0,%1,%2,%3}, [%4];" \
        : "=r"(r0), "=r"(r1), "=r"(r2), "=r"(r3) : "r"(addr))

#define MMA16816(d, a, b0, b1) \
    asm volatile("mma.sync.aligned.m16n8k16.row.col.f32.f16.f16.f32 " \
        "{%0,%1,%2,%3}, {%4,%5,%6,%7}, {%8,%9}, {%0,%1,%2,%3};" \
        : "+f"((d)[0]), "+f"((d)[1]), "+f"((d)[2]), "+f"((d)[3]) \
        : "r"((a)[0]), "r"((a)[1]), "r"((a)[2]), "r"((a)[3]), "r"(b0), "r"(b1))

// ==================== fp32 -> fp16 converts ====================
__device__ __forceinline__ void conv4(const float* __restrict__ src,
                                      __half* __restrict__ hi, int i) {
    float4 x = ((const float4*)src)[i];
    __half2* hp = (__half2*)(hi + i * 4);
    hp[0] = __half2(__float2half_rn(x.x), __float2half_rn(x.y));
    hp[1] = __half2(__float2half_rn(x.z), __float2half_rn(x.w));
}

// all 4 weights + x in one launch
#define WQ4 (DMODEL*DMODEL/4)
#define WK4 (KVD*DMODEL/4)
#define X4  (SEQ*DMODEL/4)
__global__ void conv_all_kernel(const float* __restrict__ Wq, const float* __restrict__ Wk,
                                const float* __restrict__ Wv, const float* __restrict__ Wo,
                                const float* __restrict__ x,
                                __half* __restrict__ qh, __half* __restrict__ kh,
                                __half* __restrict__ vh, __half* __restrict__ oh,
                                __half* __restrict__ xh) {
    int i = blockIdx.x * blockDim.x + threadIdx.x;
    if (i < WQ4)                          conv4(Wq, qh, i);
    else if (i < WQ4 + WK4)               conv4(Wk, kh, i - WQ4);
    else if (i < WQ4 + 2*WK4)             conv4(Wv, vh, i - WQ4 - WK4);
    else if (i < 2*WQ4 + 2*WK4)           conv4(Wo, oh, i - WQ4 - 2*WK4);
    else if (i < 2*WQ4 + 2*WK4 + X4)      conv4(x, xh, i - 2*WQ4 - 2*WK4);
}

// ==================== HMMA fp16 GEMM (projections, 1-term) ====================
#define BK 32
#define ASTRH 40
#define TILEB (128 * ASTRH * 2)     // 10240 bytes
#define GSMEM (TILEB * 4)           // 2 stages x 2 tiles = 40960

__global__ void __launch_bounds__(256, 2) gemm1(
    const __half* __restrict__ Ahi,
    const __half* __restrict__ B0h,
    float* __restrict__ C0a, float* __restrict__ C0b, int N0, int nx0,
    const __half* __restrict__ B1h,
    float* __restrict__ C1a, float* __restrict__ C1b, int N1, int nx1,
    const __half* __restrict__ B2h,
    float* __restrict__ C2a, float* __restrict__ C2b, int N2,
    int K, int Khalf) {
    extern __shared__ __half gsm[];
    const int bx = blockIdx.x;
    const int z = blockIdx.z;
    const __half *Bh; float* C; int Nc, bnl;
    if (bx < nx0)            { Bh = B0h; C = z ? C0b : C0a; Nc = N0; bnl = bx * 128; }
    else if (bx < nx0 + nx1) { Bh = B1h; C = z ? C1b : C1a; Nc = N1; bnl = (bx - nx0) * 128; }
    else                     { Bh = B2h; C = z ? C2b : C2a; Nc = N2; bnl = (bx - nx0 - nx1) * 128; }
    const int koff = z * Khalf;

    const int tid = threadIdx.x;
    const int wid = tid >> 5, lane = tid & 31;
    const int wm = (wid & 1) * 64;
    const int wn = (wid >> 1) * 32;
    const int bm = blockIdx.y * 128;
    const int lr = lane & 15, lc = lane >> 4;

    uint32_t sbu = smem_u32(gsm);
    const int r0_ = tid >> 2, r1_ = r0_ + 64;
    const int pp = (tid & 3) * 8;

    float acc[4][4][4];
#pragma unroll
    for (int a = 0; a < 4; a++)
#pragma unroll
        for (int b = 0; b < 4; b++)
#pragma unroll
            for (int c = 0; c < 4; c++) acc[a][b][c] = 0.f;

#define LOADCHUNK(st, k0) do {                                                  \
    uint32_t _b = sbu + (st) * (2 * TILEB);                                     \
    CP_ASYNC16(_b + (r0_ * ASTRH + pp) * 2,                                     \
               Ahi + (size_t)(bm + r0_) * K + (k0) + pp);                       \
    CP_ASYNC16(_b + (r1_ * ASTRH + pp) * 2,                                     \
               Ahi + (size_t)(bm + r1_) * K + (k0) + pp);                       \
    CP_ASYNC16(_b + TILEB + (r0_ * ASTRH + pp) * 2,                             \
               Bh + (size_t)(bnl + r0_) * K + (k0) + pp);                       \
    CP_ASYNC16(_b + TILEB + (r1_ * ASTRH + pp) * 2,                             \
               Bh + (size_t)(bnl + r1_) * K + (k0) + pp);                       \
} while (0)

    const int kiters = Khalf / BK;
    LOADCHUNK(0, koff);
    CP_COMMIT();

    for (int i = 0; i < kiters; i++) {
        int s = i & 1;
        CP_WAIT_0();
        __syncthreads();
        if (i + 1 < kiters) {
            LOADCHUNK(s ^ 1, koff + (i + 1) * BK);
            CP_COMMIT();
        }

        uint32_t base = sbu + s * (2 * TILEB);
#pragma unroll
        for (int k16 = 0; k16 < 2; k16++) {
            int koff16 = k16 * 16 + lc * 8;
            uint32_t aH[4][4], bH[2][4];
#pragma unroll
            for (int mt = 0; mt < 4; mt++) {
                uint32_t adr = base + ((wm + mt * 16 + lr) * ASTRH + koff16) * 2;
                LDSM4(aH[mt][0], aH[mt][1], aH[mt][2], aH[mt][3], adr);
            }
#pragma unroll
            for (int p = 0; p < 2; p++) {
                uint32_t adr = base + TILEB + ((wn + p * 16 + lr) * ASTRH + koff16) * 2;
                LDSM4(bH[p][0], bH[p][1], bH[p][2], bH[p][3], adr);
            }
#pragma unroll
            for (int mt = 0; mt < 4; mt++)
#pragma unroll
                for (int nt = 0; nt < 4; nt++) {
                    int p = nt >> 1, w = nt & 1;
                    MMA16816(acc[mt][nt], aH[mt], bH[p][w], bH[p][w + 2]);
                }
        }
    }

    int er = lane >> 2, ec = (lane & 3) * 2;
#pragma unroll
    for (int mt = 0; mt < 4; mt++) {
#pragma unroll
        for (int nt = 0; nt < 4; nt++) {
            int r = bm + wm + mt * 16 + er;
            int c = bnl + wn + nt * 8 + ec;
            *(float2*)&C[(size_t)r * Nc + c]       = make_float2(acc[mt][nt][0], acc[mt][nt][1]);
            *(float2*)&C[(size_t)(r + 8) * Nc + c] = make_float2(acc[mt][nt][2], acc[mt][nt][3]);
        }
    }
}

// -------------------- RoPE --------------------
__global__ void rope_table_kernel(const int* __restrict__ start_pos) {
    int idx = blockIdx.x * blockDim.x + threadIdx.x;
    if (idx >= SEQ * 32) return;
    int t = idx >> 5, j = idx & 31;
    const double PI = 3.14159265358979323846;
    double e = (double)(2 * j) / 64.0;
    double invf = pow(500000.0, -e);
    double wavelen = 2.0 * PI / invf;
    double inv;
    if (wavelen > 8192.0) {
        inv = invf / 32.0;
    } else if (wavelen < 2048.0) {
        inv = invf;
    } else {
        double smooth = (8192.0 / wavelen - 1.0) / 3.0;
        inv = (1.0 - smooth) * (invf / 32.0) + smooth * invf;
    }
    float angle = (float)(start_pos[0] + t) * (float)inv;
    g_cos[idx] = (float)cos((double)angle);
    g_sin[idx] = (float)sin((double)angle);
}

// fused: partial-add + RoPE + fp16 convert for q,k, and partial-add + convert for v
#define ROPE_TOTAL (SEQ * 40 * 32)
#define V4 (SEQ*KVD/4)
__global__ void rope_conv_all_kernel(const float* __restrict__ q0, const float* __restrict__ q1,
                                     const float* __restrict__ k0, const float* __restrict__ k1,
                                     const float* __restrict__ v0, const float* __restrict__ v1,
                                     __half* __restrict__ qhi, __half* __restrict__ khi,
                                     __half* __restrict__ vhi) {
    int idx = blockIdx.x * blockDim.x + threadIdx.x;
    if (idx < ROPE_TOTAL) {
        int j = idx & 31;
        int hh = (idx >> 5) % 40;
        int t = idx / (32 * 40);
        float c = g_cos[t * 32 + j];
        float s = g_sin[t * 32 + j];
        if (hh < NH) {
            size_t off = (size_t)t * DMODEL + hh * 64 + j;
            float x1 = q0[off]      + q1[off];
            float x2 = q0[off + 32] + q1[off + 32];
            qhi[off]      = __float2half_rn(x1 * c - x2 * s);
            qhi[off + 32] = __float2half_rn(x2 * c + x1 * s);
        } else {
            size_t off = (size_t)t * KVD + (hh - NH) * 64 + j;
            float x1 = k0[off]      + k1[off];
            float x2 = k0[off + 32] + k1[off + 32];
            khi[off]      = __float2half_rn(x1 * c - x2 * s);
            khi[off + 32] = __float2half_rn(x2 * c + x1 * s);
        }
    } else {
        int i = idx - ROPE_TOTAL;
        if (i >= V4) return;
        float4 a = ((const float4*)v0)[i];
        float4 b = ((const float4*)v1)[i];
        __half2* hp = (__half2*)(vhi + i * 4);
        hp[0] = __floats2half2_rn(a.x + b.x, a.y + b.y);
        hp[1] = __floats2half2_rn(a.z + b.z, a.w + b.w);
    }
}

// ==================== HMMA flash attention (full 1-term) ====================
#define FATR 72
#define FTILE (64 * FATR * 2)
#define FLASH_SMEM (FTILE * 5)   // Qh + 2 stages x (Kh, Vh)

__global__ void __launch_bounds__(128) flash_hmma(
    const __half* __restrict__ qhi,
    const __half* __restrict__ khi,
    const __half* __restrict__ vhi,
    __half* __restrict__ chi) {
    extern __shared__ __half fsm[];
    const int h  = blockIdx.x;
    const int qb = gridDim.y - 1 - blockIdx.y;
    const int g  = h >> 2;
    const int tid = threadIdx.x;
    const int wid = tid >> 5, lane = tid & 31;
    const int wm = wid * 16;
    const int er = lane >> 2, ec = (lane & 3) * 2;
    const int lr = lane & 15, lc = lane >> 4;

    uint32_t sb = smem_u32(fsm);
    uint32_t sQh = sb;

#pragma unroll
    for (int l = 0; l < 4; l++) {
        int c = tid + l * 128;
        int row = c >> 3, cc = c & 7;
        size_t off = (size_t)(qb * 64 + row) * DMODEL + h * 64 + cc * 8;
        CP_ASYNC16(sQh + row * FATR * 2 + cc * 16, qhi + off);
    }
#define KV_LOAD(kb_, st_) do {                                                  \
    uint32_t base = sb + FTILE + (st_) * 2 * FTILE;                             \
    _Pragma("unroll")                                                           \
    for (int l = 0; l < 4; l++) {                                               \
        int c = tid + l * 128;                                                  \
        int row = c >> 3, cc = c & 7;                                           \
        size_t off = (size_t)((kb_) * 64 + row) * KVD + g * 64 + cc * 8;        \
        uint32_t d = row * FATR * 2 + cc * 16;                                  \
        CP_ASYNC16(base + d, khi + off);                                        \
        CP_ASYNC16(base + FTILE + d, vhi + off);                                \
    }                                                                           \
} while (0)

    KV_LOAD(0, 0);
    CP_COMMIT();

    uint32_t aQh[4][4];
    float oacc[8][4];
    float mi0 = -INFINITY, mi1 = -INFINITY, li0 = 0.f, li1 = 0.f;
#pragma unroll
    for (int nt = 0; nt < 8; nt++)
#pragma unroll
        for (int j = 0; j < 4; j++) oacc[nt][j] = 0.f;

    for (int kb = 0; kb <= qb; kb++) {
        int stage = kb & 1;
        CP_WAIT_0();
        __syncthreads();
        if (kb < qb) {
            KV_LOAD(kb + 1, stage ^ 1);
            CP_COMMIT();
        }

        if (kb == 0) {
#pragma unroll
            for (int k16 = 0; k16 < 4; k16++) {
                uint32_t ah = sQh + ((wm + lr) * FATR + k16 * 16 + lc * 8) * 2;
                LDSM4(aQh[k16][0], aQh[k16][1], aQh[k16][2], aQh[k16][3], ah);
            }
        }

        uint32_t base = sb + FTILE + stage * 2 * FTILE;
        uint32_t sKh = base, sVh = base + FTILE;

        float sacc[8][4];
#pragma unroll
        for (int nt = 0; nt < 8; nt++)
#pragma unroll
            for (int j = 0; j < 4; j++) sacc[nt][j] = 0.f;

#pragma unroll
        for (int k16 = 0; k16 < 4; k16++) {
            uint32_t bh[4][4];
#pragma unroll
            for (int p = 0; p < 4; p++) {
                uint32_t adr = sKh + ((p * 16 + lr) * FATR + k16 * 16 + lc * 8) * 2;
                LDSM4(bh[p][0], bh[p][1], bh[p][2], bh[p][3], adr);
            }
#pragma unroll
            for (int nt = 0; nt < 8; nt++) {
                int p = nt >> 1, w = nt & 1;
                MMA16816(sacc[nt], aQh[k16], bh[p][w], bh[p][w + 2]);
            }
        }

        if (kb == qb) {
#pragma unroll
            for (int nt = 0; nt < 8; nt++) {
                int c0 = nt * 8 + ec;
                sacc[nt][0] = (c0     <= wm + er)     ? sacc[nt][0] * 0.125f : -INFINITY;
                sacc[nt][1] = (c0 + 1 <= wm + er)     ? sacc[nt][1] * 0.125f : -INFINITY;
                sacc[nt][2] = (c0     <= wm + er + 8) ? sacc[nt][2] * 0.125f : -INFINITY;
                sacc[nt][3] = (c0 + 1 <= wm + er + 8) ? sacc[nt][3] * 0.125f : -INFINITY;
            }
        } else {
#pragma unroll
            for (int nt = 0; nt < 8; nt++)
#pragma unroll
                for (int j = 0; j < 4; j++) sacc[nt][j] *= 0.125f;
        }

        float mx0 = -INFINITY, mx1 = -INFINITY;
#pragma unroll
        for (int nt = 0; nt < 8; nt++) {
            mx0 = fmaxf(mx0, fmaxf(sacc[nt][0], sacc[nt][1]));
            mx1 = fmaxf(mx1, fmaxf(sacc[nt][2], sacc[nt][3]));
        }
#pragma unroll
        for (int off = 1; off < 4; off <<= 1) {
            mx0 = fmaxf(mx0, __shfl_xor_sync(0xffffffffu, mx0, off));
            mx1 = fmaxf(mx1, __shfl_xor_sync(0xffffffffu, mx1, off));
        }
        float mn0 = fmaxf(mi0, mx0), mn1 = fmaxf(mi1, mx1);
        float sum0 = 0.f, sum1 = 0.f;
#pragma unroll
        for (int nt = 0; nt < 8; nt++) {
            sacc[nt][0] = __expf(sacc[nt][0] - mn0);
            sacc[nt][1] = __expf(sacc[nt][1] - mn0);
            sacc[nt][2] = __expf(sacc[nt][2] - mn1);
            sacc[nt][3] = __expf(sacc[nt][3] - mn1);
            sum0 += sacc[nt][0] + sacc[nt][1];
            sum1 += sacc[nt][2] + sacc[nt][3];
        }
#pragma unroll
        for (int off = 1; off < 4; off <<= 1) {
            sum0 += __shfl_xor_sync(0xffffffffu, sum0, off);
            sum1 += __shfl_xor_sync(0xffffffffu, sum1, off);
        }
        float sc0 = __expf(mi0 - mn0), sc1 = __expf(mi1 - mn1);
        li0 = li0 * sc0 + sum0; li1 = li1 * sc1 + sum1;
        mi0 = mn0; mi1 = mn1;
#pragma unroll
        for (int nt = 0; nt < 8; nt++) {
            oacc[nt][0] *= sc0; oacc[nt][1] *= sc0;
            oacc[nt][2] *= sc1; oacc[nt][3] *= sc1;
        }

#pragma unroll
        for (int k16 = 0; k16 < 4; k16++) {
            uint32_t ph[4];
#pragma unroll
            for (int half16 = 0; half16 < 2; half16++) {
                int st = 2 * k16 + half16;
                __half2 h01 = __floats2half2_rn(sacc[st][0], sacc[st][1]);
                __half2 h23 = __floats2half2_rn(sacc[st][2], sacc[st][3]);
                ph[half16 * 2]     = *(uint32_t*)&h01;
                ph[half16 * 2 + 1] = *(uint32_t*)&h23;
            }
            uint32_t bvh[4][4];
#pragma unroll
            for (int p = 0; p < 4; p++) {
                uint32_t adr = sVh + ((k16 * 16 + lr) * FATR + p * 16 + lc * 8) * 2;
                LDSM4T(bvh[p][0], bvh[p][1], bvh[p][2], bvh[p][3], adr);
            }
#pragma unroll
            for (int nt = 0; nt < 8; nt++) {
                int p = nt >> 1, w = (nt & 1) * 2;
                MMA16816(oacc[nt], ph, bvh[p][w], bvh[p][w + 1]);
            }
        }
    }

    float inv0 = 1.0f / li0, inv1 = 1.0f / li1;
    int r0g = qb * 64 + wm + er, r1g = r0g + 8;
#pragma unroll
    for (int nt = 0; nt < 8; nt++) {
        int c = h * 64 + nt * 8 + ec;
        __half2 h0 = __floats2half2_rn(oacc[nt][0] * inv0, oacc[nt][1] * inv0);
        __half2 h1 = __floats2half2_rn(oacc[nt][2] * inv1, oacc[nt][3] * inv1);
        *(__half2*)&chi[(size_t)r0g * DMODEL + c] = h0;
        *(__half2*)&chi[(size_t)r1g * DMODEL + c] = h1;
    }
}

// -------------------- launch --------------------
extern "C" void kernel_launch(void* const* d_in, const int* in_sizes, int n_in,
                              void* d_out, int out_size) {
    const float* x  = (const float*)d_in[0];
    const float* Wq = (const float*)d_in[1];
    const float* Wk = (const float*)d_in[2];
    const float* Wv = (const float*)d_in[3];
    const float* Wo = (const float*)d_in[4];
    const int* start_pos = (const int*)d_in[5];
    float* out = (float*)d_out;

    float *qp, *kp, *vp, *qp2, *kp2, *vp2;
    cudaGetSymbolAddress((void**)&qp, g_q);   cudaGetSymbolAddress((void**)&qp2, g_q2);
    cudaGetSymbolAddress((void**)&kp, g_k);   cudaGetSymbolAddress((void**)&kp2, g_k2);
    cudaGetSymbolAddress((void**)&vp, g_v);   cudaGetSymbolAddress((void**)&vp2, g_v2);
    __half *xhi, *wqhi, *wkhi, *wvhi, *wohi;
    __half *chi, *qh, *kh, *vh;
    cudaGetSymbolAddress((void**)&xhi, g_xhi);
    cudaGetSymbolAddress((void**)&wqhi, g_wqhi);
    cudaGetSymbolAddress((void**)&wkhi, g_wkhi);
    cudaGetSymbolAddress((void**)&wvhi, g_wvhi);
    cudaGetSymbolAddress((void**)&wohi, g_wohi);
    cudaGetSymbolAddress((void**)&chi, g_chi);
    cudaGetSymbolAddress((void**)&qh, g_qh);
    cudaGetSymbolAddress((void**)&kh, g_kh);
    cudaGetSymbolAddress((void**)&vh, g_vh);

    cudaFuncSetAttribute(gemm1, cudaFuncAttributeMaxDynamicSharedMemorySize, GSMEM);
    cudaFuncSetAttribute(flash_hmma, cudaFuncAttributeMaxDynamicSharedMemorySize,
                         FLASH_SMEM);

    // 0: all converts (4 weights + x) in one launch
    conv_all_kernel<<<(2*WQ4 + 2*WK4 + X4 + 255) / 256, 256>>>(
        Wq, Wk, Wv, Wo, x, wqhi, wkhi, wvhi, wohi, xhi);
    // 1: rope tables
    rope_table_kernel<<<(SEQ * 32 + 255) / 256, 256>>>(start_pos);
    // 2: fused Q/K/V projection, split-K=2
    gemm1<<<dim3(24, SEQ/128, 2), 256, GSMEM>>>(
        xhi,
        wqhi, qp, qp2, DMODEL, 16,
        wkhi, kp, kp2, KVD, 4,
        wvhi, vp, vp2, KVD,
        DMODEL, DMODEL/2);
    // 3: fused partial-add + rope + convert (q,k) and partial-add + convert (v)
    rope_conv_all_kernel<<<(ROPE_TOTAL + V4 + 255) / 256, 256>>>(
        qp, qp2, kp, kp2, vp, vp2, qh, kh, vh);
    // 4: flash attention (1-term) -> ctx fp16
    flash_hmma<<<dim3(NH, SEQ / 64), 128, FLASH_SMEM>>>(qh, kh, vh, chi);
    // 5: O projection (single wave), 1-term
    gemm1<<<dim3(16, SEQ/128, 1), 256, GSMEM>>>(
        chi,
        wohi, out, out, DMODEL, 16,
        wohi, out, out, DMODEL, 0,
        wohi, out, out, DMODEL,
        DMODEL, DMODEL);
}